// round 15
// baseline (speedup 1.0000x reference)
#include <cuda_runtime.h>
#include <math.h>
#include <stdint.h>

#define T_STEPS 1000
#define N_B     64
#define H_DIM   1024
#define C_DIM   256
#define G3      768

typedef unsigned long long ull;

// Scratch (__device__ globals; allocation-free rule)
__device__ float g_xpT[(size_t)T_STEPS * G3 * N_B];   // [t][gate*256+c][n]
__device__ float g_hEx[16 * 1024];                     // per-cluster h exchange
__device__ float g_Ah[(size_t)64000 * 1024];           // pre-split enc (tf32 hi)
__device__ float g_Al[(size_t)64000 * 1024];           // pre-split enc (tf32 lo)
__device__ float g_Bh[(size_t)G3 * 1024];              // pre-split W_ih hi
__device__ float g_Bl[(size_t)G3 * 1024];              // pre-split W_ih lo

__device__ __forceinline__ float tf32_round(float f) {
    uint32_t r;
    asm("cvt.rna.tf32.f32 %0, %1;" : "=r"(r) : "f"(f));
    return __uint_as_float(r);
}
__device__ __forceinline__ void tf32_split(float x, float& hi, float& lo) {
    hi = tf32_round(x);
    lo = tf32_round(x - hi);
}
__device__ __forceinline__ void cp_async16(uint32_t smem_addr, const void* gptr) {
    asm volatile("cp.async.cg.shared.global [%0], [%1], 16;" :: "r"(smem_addr), "l"(gptr));
}
// packed f32x2 fma: d = a*b + d (2 exact fp32-rn MACs / instr)
__device__ __forceinline__ void fma2(ull& d, ull a, ull b) {
    asm("fma.rn.f32x2 %0, %1, %2, %3;" : "=l"(d) : "l"(a), "l"(b), "l"(d));
}
__device__ __forceinline__ float hsum2(ull a) {
    float x, y;
    asm("mov.b64 {%0,%1}, %2;" : "=f"(x), "=f"(y) : "l"(a));
    return x + y;
}

#define MMA_TF32(d, a, b)                                                       \
    asm volatile(                                                               \
        "mma.sync.aligned.m16n8k8.row.col.f32.tf32.tf32.f32 "                   \
        "{%0,%1,%2,%3}, {%4,%5,%6,%7}, {%8,%9}, {%0,%1,%2,%3};"                 \
        : "+f"(d[0]), "+f"(d[1]), "+f"(d[2]), "+f"(d[3])                        \
        : "r"(a[0]), "r"(a[1]), "r"(a[2]), "r"(a[3]), "r"(b[0]), "r"(b[1]))

#define BM 128
#define BN 128
#define BK 16
#define LDP 20
#define TILE_F (BM * LDP)
#define STAGE_F (4 * TILE_F)
#define GEMM_SMEM_BYTES (2 * STAGE_F * 4)   // 81920

// ---------------------------------------------------------------------------
// Kernel 0: one-shot tf32 split of enc and W_ih into hi/lo (VERBATIM r14).
// ---------------------------------------------------------------------------
__global__ void __launch_bounds__(256) split_ab(const float4* __restrict__ A,
                                                const float4* __restrict__ W)
{
    const int NA4 = 16384000;
    const int NW4 = 196608;
    float4* Ah4 = (float4*)g_Ah;  float4* Al4 = (float4*)g_Al;
    float4* Bh4 = (float4*)g_Bh;  float4* Bl4 = (float4*)g_Bl;
    for (int i = blockIdx.x * blockDim.x + threadIdx.x; i < NA4 + NW4;
         i += gridDim.x * blockDim.x) {
        bool isA = i < NA4;
        float4 v = isA ? __ldg(A + i) : __ldg(W + (i - NA4));
        float4 h, l;
        tf32_split(v.x, h.x, l.x);
        tf32_split(v.y, h.y, l.y);
        tf32_split(v.z, h.z, l.z);
        tf32_split(v.w, h.w, l.w);
        if (isA) { Ah4[i] = h; Al4[i] = l; }
        else     { Bh4[i - NA4] = h; Bl4[i - NA4] = l; }
    }
}

// ---------------------------------------------------------------------------
// Kernel 1: 3xTF32 tensor-core GEMM, cp.async double-buffered (VERBATIM r14).
// ---------------------------------------------------------------------------
__global__ void __launch_bounds__(256) gemm_xp_tc(const float* __restrict__ bih)
{
    extern __shared__ float smg[];

    const int tid  = threadIdx.x;
    const int m0   = blockIdx.y * BM;
    const int g0   = blockIdx.x * BN;
    const int warp = tid >> 5;
    const int lane = tid & 31;
    const int wm   = (warp & 1) * 64;
    const int wn   = (warp >> 1) * 32;
    const int lr_  = lane >> 2;
    const int lc_  = lane & 3;

    const uint32_t sm_u = (uint32_t)__cvta_generic_to_shared(smg);

    const int mat   = warp >> 1;
    const int rhalf = (warp & 1) * 64;
    const float* gsrc =
        (mat == 0) ? (g_Ah + (size_t)m0 * H_DIM) :
        (mat == 1) ? (g_Al + (size_t)m0 * H_DIM) :
        (mat == 2) ? (g_Bh + (size_t)g0 * H_DIM) :
                     (g_Bl + (size_t)g0 * H_DIM);

    auto issue_tile = [&](int stage, int k0) {
        #pragma unroll
        for (int i = 0; i < 8; ++i) {
            int chunk = i * 32 + lane;
            int rowl  = chunk >> 2;
            int ch    = chunk & 3;
            int row   = rhalf + rowl;
            const float* src = gsrc + (size_t)row * H_DIM + k0 + ch * 4;
            uint32_t dst = sm_u +
                (uint32_t)((stage * STAGE_F + mat * TILE_F + row * LDP + ch * 4) * 4);
            cp_async16(dst, src);
        }
        asm volatile("cp.async.commit_group;" ::: "memory");
    };

    float acc[4][4][4];
    #pragma unroll
    for (int mi = 0; mi < 4; ++mi)
        #pragma unroll
        for (int ni = 0; ni < 4; ++ni)
            #pragma unroll
            for (int r = 0; r < 4; ++r) acc[mi][ni][r] = 0.f;

    issue_tile(0, 0);
    issue_tile(1, BK);

    int p = 0;
    for (int it = 0; it < H_DIM / BK; ++it) {
        asm volatile("cp.async.wait_group 1;" ::: "memory");
        __syncthreads();

        const float* S  = smg + p * STAGE_F;
        const float* Ah = S;
        const float* Al = S + TILE_F;
        const float* Bh = S + 2 * TILE_F;
        const float* Bl = S + 3 * TILE_F;

        #pragma unroll
        for (int kk = 0; kk < 2; ++kk) {
            const int kb = kk * 8;
            uint32_t afh[4][4], afl[4][4];
            #pragma unroll
            for (int mi = 0; mi < 4; ++mi) {
                int r = wm + mi * 16 + lr_;
                afh[mi][0] = __float_as_uint(Ah[r * LDP + kb + lc_]);
                afh[mi][1] = __float_as_uint(Ah[(r + 8) * LDP + kb + lc_]);
                afh[mi][2] = __float_as_uint(Ah[r * LDP + kb + lc_ + 4]);
                afh[mi][3] = __float_as_uint(Ah[(r + 8) * LDP + kb + lc_ + 4]);
                afl[mi][0] = __float_as_uint(Al[r * LDP + kb + lc_]);
                afl[mi][1] = __float_as_uint(Al[(r + 8) * LDP + kb + lc_]);
                afl[mi][2] = __float_as_uint(Al[r * LDP + kb + lc_ + 4]);
                afl[mi][3] = __float_as_uint(Al[(r + 8) * LDP + kb + lc_ + 4]);
            }
            uint32_t bfh[4][2], bfl[4][2];
            #pragma unroll
            for (int ni = 0; ni < 4; ++ni) {
                int cn = wn + ni * 8 + lr_;
                bfh[ni][0] = __float_as_uint(Bh[cn * LDP + kb + lc_]);
                bfh[ni][1] = __float_as_uint(Bh[cn * LDP + kb + lc_ + 4]);
                bfl[ni][0] = __float_as_uint(Bl[cn * LDP + kb + lc_]);
                bfl[ni][1] = __float_as_uint(Bl[cn * LDP + kb + lc_ + 4]);
            }
            #pragma unroll
            for (int mi = 0; mi < 4; ++mi)
                #pragma unroll
                for (int ni = 0; ni < 4; ++ni) {
                    MMA_TF32(acc[mi][ni], afl[mi], bfh[ni]);
                    MMA_TF32(acc[mi][ni], afh[mi], bfl[ni]);
                    MMA_TF32(acc[mi][ni], afh[mi], bfh[ni]);
                }
        }
        __syncthreads();
        if (it + 2 < H_DIM / BK) issue_tile(p, (it + 2) * BK);
        p ^= 1;
    }

    #pragma unroll
    for (int mi = 0; mi < 4; ++mi) {
        int row = m0 + wm + mi * 16 + lr_;
        int t   = row >> 6;
        int n   = row & 63;
        #pragma unroll
        for (int ni = 0; ni < 4; ++ni) {
            int col = g0 + wn + ni * 8 + 2 * lc_;
            float bv0 = __ldg(&bih[col]);
            float bv1 = __ldg(&bih[col + 1]);
            float* p0 = &g_xpT[((size_t)t * G3 + col) * N_B];
            float* p1 = &g_xpT[((size_t)t * G3 + col + 1) * N_B];
            p0[n]     = acc[mi][ni][0] + bv0;
            p1[n]     = acc[mi][ni][1] + bv1;
            p0[n + 8] = acc[mi][ni][2] + bv0;
            p1[n + 8] = acc[mi][ni][3] + bv1;
        }
    }
}

// ---------------------------------------------------------------------------
// Kernel 2: cluster-parallel GRU scan — r14 structure, ONE change:
// packed fma.rn.f32x2 dot with W in smem, layout [g][ch][k] (k-contiguous,
// row stride 258 -> LDS.64 at the 2-phase floor; h loads stay broadcast).
// Halves the FMA-issue floor 1536 -> 768 cyc/SMSP/step; regs stay low.
// ---------------------------------------------------------------------------
#define CL_CTAS 8
#define SCAN_THR 256
#define KPAD 258
#define W2_FLOATS (3 * 32 * KPAD)     // 24768
#define H_FLOATS  1024
#define RED_STRIDE 13
#define RED_FLOATS (SCAN_THR * RED_STRIDE)
#define SCAN_SMEM_BYTES ((W2_FLOATS + H_FLOATS + RED_FLOATS) * 4)

#define CLUSTER_SYNC() do {                                          \
    asm volatile("barrier.cluster.arrive.aligned;" ::: "memory");    \
    asm volatile("barrier.cluster.wait.aligned;" ::: "memory");      \
} while (0)

__device__ __forceinline__ float fast_sigmoid(float x) {
    return __fdividef(1.f, 1.f + __expf(-x));
}
__device__ __forceinline__ float fast_tanh(float x) {
    return 1.f - __fdividef(2.f, __expf(2.f * x) + 1.f);
}

__global__ void __launch_bounds__(SCAN_THR, 1) __cluster_dims__(CL_CTAS, 1, 1)
scan_cluster(const float* __restrict__ Whh,
             const float* __restrict__ bhh,
             float* __restrict__ out)
{
    extern __shared__ float sm[];
    float* W_s = sm;                    // [3][32][258]  (g, ch, k padded)
    float* h_s = sm + W2_FLOATS;        // [4][256]      (row, k)
    float* red = h_s + H_FLOATS;        // [256][13]

    const int tid  = threadIdx.x;
    const int cl   = blockIdx.x >> 3;
    const int rank = blockIdx.x & 7;
    const int chl  = tid & 31;          // dot role: local channel
    const int ks   = tid >> 5;          // dot role: k-chunk 0..7
    const int k0   = ks * 32;

    const int rrow = tid >> 5;          // reducer role (tid<128)
    const int rchl = tid & 31;
    const int c_g  = rank * 32 + rchl;
    const int n_g  = cl * 4 + rrow;

    // W slice: W_s[(g*32 + lchl)*KPAD + k] = Whh[(g*256 + rank*32 + lchl)*256 + k]
    for (int idx = tid; idx < 3 * 32 * 256; idx += SCAN_THR) {
        int k    = idx & 255;
        int lchl = (idx >> 8) & 31;
        int g    = idx >> 13;
        W_s[(g * 32 + lchl) * KPAD + k] =
            __ldg(&Whh[((size_t)(g * C_DIM + rank * 32 + lchl)) * C_DIM + k]);
    }
    #pragma unroll
    for (int i = 0; i < H_FLOATS / SCAN_THR; ++i)
        h_s[tid + i * SCAN_THR] = 0.f;

    float bhr = 0.f, bhz = 0.f, bhn = 0.f;
    if (tid < 128) {
        bhr = __ldg(&bhh[c_g]);
        bhz = __ldg(&bhh[C_DIM + c_g]);
        bhn = __ldg(&bhh[2 * C_DIM + c_g]);
    }
    __syncthreads();

    const ull* Wr = (const ull*)(W_s + (0 * 32 + chl) * KPAD + k0);
    const ull* Wz = (const ull*)(W_s + (1 * 32 + chl) * KPAD + k0);
    const ull* Wn = (const ull*)(W_s + (2 * 32 + chl) * KPAD + k0);
    const ull* h0p = (const ull*)(h_s + 0 * C_DIM + k0);
    const ull* h1p = (const ull*)(h_s + 1 * C_DIM + k0);
    const ull* h2p = (const ull*)(h_s + 2 * C_DIM + k0);
    const ull* h3p = (const ull*)(h_s + 3 * C_DIM + k0);

    for (int t = 0; t < T_STEPS; ++t) {
        float xr = 0.f, xz = 0.f, xn = 0.f;
        if (tid < 128) {
            const float* xp = g_xpT + (size_t)t * (G3 * N_B);
            xr = __ldg(xp + (0 * C_DIM + c_g) * N_B + n_g);
            xz = __ldg(xp + (1 * C_DIM + c_g) * N_B + n_g);
            xn = __ldg(xp + (2 * C_DIM + c_g) * N_B + n_g);
        }

        // packed dot over own 32-k chunk: a2[row][gate], 2 lanes each
        ull a2[4][3];
        #pragma unroll
        for (int rw = 0; rw < 4; ++rw)
            #pragma unroll
            for (int g = 0; g < 3; ++g) a2[rw][g] = 0ull;

        if (t > 0) {
            #pragma unroll
            for (int j = 0; j < 16; ++j) {
                ull h0 = h0p[j], h1 = h1p[j], h2 = h2p[j], h3 = h3p[j];  // broadcast
                ull wr = Wr[j], wz = Wz[j], wn = Wn[j];
                fma2(a2[0][0], h0, wr); fma2(a2[0][1], h0, wz); fma2(a2[0][2], h0, wn);
                fma2(a2[1][0], h1, wr); fma2(a2[1][1], h1, wz); fma2(a2[1][2], h1, wn);
                fma2(a2[2][0], h2, wr); fma2(a2[2][1], h2, wz); fma2(a2[2][2], h2, wn);
                fma2(a2[3][0], h3, wr); fma2(a2[3][1], h3, wz); fma2(a2[3][2], h3, wn);
            }
        }

        {
            float* rp = &red[tid * RED_STRIDE];
            #pragma unroll
            for (int rw = 0; rw < 4; ++rw)
                #pragma unroll
                for (int g = 0; g < 3; ++g) rp[rw * 3 + g] = hsum2(a2[rw][g]);
        }
        __syncthreads();

        float hnew = 0.f;
        if (tid < 128) {
            float sr = 0.f, sz = 0.f, sn = 0.f;
            #pragma unroll
            for (int kq = 0; kq < 8; ++kq) {
                const float* rp = &red[((kq << 5) + rchl) * RED_STRIDE + rrow * 3];
                sr += rp[0];
                sz += rp[1];
                sn += rp[2];
            }
            float h_old = h_s[rrow * 256 + c_g];

            float r  = fast_sigmoid(xr + sr + bhr);
            float z  = fast_sigmoid(xz + sz + bhz);
            float nt = fast_tanh(xn + r * (sn + bhn));
            hnew = nt + z * (h_old - nt);

            __stcg(&g_hEx[cl * 1024 + rrow * 256 + c_g], hnew);
        }

        CLUSTER_SYNC();   // arrive=release / wait=acquire orders g_hEx stores

        if (tid < 128)
            out[((size_t)t * N_B + n_g) * C_DIM + c_g] = hnew;  // off skew path

        if (t < T_STEPS - 1) {
            ((float4*)h_s)[tid] = __ldcg((const float4*)(g_hEx + cl * 1024) + tid);
            __syncthreads();
        }
    }
}

// ---------------------------------------------------------------------------
// Kernel 3: log-softmax over c, in place on [t][n][c]. Warp per row. (r14)
// ---------------------------------------------------------------------------
__global__ void __launch_bounds__(256) logsoftmax_kernel(float* __restrict__ out)
{
    const int t    = blockIdx.x;
    const int w    = threadIdx.x >> 5;
    const int lane = threadIdx.x & 31;

    #pragma unroll
    for (int i = 0; i < 8; ++i) {
        const int n = w * 8 + i;
        float* row = out + ((size_t)t * N_B + n) * C_DIM;
        float4 a = *(const float4*)&row[lane * 4];
        float4 b = *(const float4*)&row[128 + lane * 4];

        float mx = fmaxf(fmaxf(fmaxf(a.x, a.y), fmaxf(a.z, a.w)),
                         fmaxf(fmaxf(b.x, b.y), fmaxf(b.z, b.w)));
        #pragma unroll
        for (int s = 16; s > 0; s >>= 1)
            mx = fmaxf(mx, __shfl_xor_sync(0xffffffffu, mx, s));

        float sum = expf(a.x - mx) + expf(a.y - mx) + expf(a.z - mx) + expf(a.w - mx)
                  + expf(b.x - mx) + expf(b.y - mx) + expf(b.z - mx) + expf(b.w - mx);
        #pragma unroll
        for (int s = 16; s > 0; s >>= 1)
            sum += __shfl_xor_sync(0xffffffffu, sum, s);

        float lse = mx + logf(sum);
        a.x -= lse; a.y -= lse; a.z -= lse; a.w -= lse;
        b.x -= lse; b.y -= lse; b.z -= lse; b.w -= lse;
        *(float4*)&row[lane * 4]       = a;
        *(float4*)&row[128 + lane * 4] = b;
    }
}

extern "C" void kernel_launch(void* const* d_in, const int* in_sizes, int n_in,
                              void* d_out, int out_size)
{
    const float* enc  = (const float*)d_in[0];
    const float* W_ih = (const float*)d_in[1];
    const float* W_hh = (const float*)d_in[2];
    const float* b_ih = (const float*)d_in[3];
    const float* b_hh = (const float*)d_in[4];
    float* out = (float*)d_out;

    cudaFuncSetAttribute(gemm_xp_tc, cudaFuncAttributeMaxDynamicSharedMemorySize, GEMM_SMEM_BYTES);
    cudaFuncSetAttribute(scan_cluster, cudaFuncAttributeMaxDynamicSharedMemorySize, SCAN_SMEM_BYTES);

    split_ab<<<8192, 256>>>((const float4*)enc, (const float4*)W_ih);
    gemm_xp_tc<<<dim3(G3 / BN, (T_STEPS * N_B) / BM), 256, GEMM_SMEM_BYTES>>>(b_ih);
    scan_cluster<<<128, SCAN_THR, SCAN_SMEM_BYTES>>>(W_hh, b_hh, out);
    logsoftmax_kernel<<<T_STEPS, 256>>>(out);
}

// round 16
// speedup vs baseline: 1.1574x; 1.1574x over previous
#include <cuda_runtime.h>
#include <math.h>
#include <stdint.h>

#define T_STEPS 1000
#define N_B     64
#define H_DIM   1024
#define C_DIM   256
#define G3      768

// Scratch (__device__ globals; allocation-free rule)
__device__ float g_xpT[(size_t)T_STEPS * G3 * N_B];   // [t][gate*256+c][n]
__device__ float g_hEx[16 * 1024];                     // per-cluster h exchange
__device__ float g_Ah[(size_t)64000 * 1024];           // pre-split enc (tf32 hi)
__device__ float g_Al[(size_t)64000 * 1024];           // pre-split enc (tf32 lo)
__device__ float g_Bh[(size_t)G3 * 1024];              // pre-split W_ih hi
__device__ float g_Bl[(size_t)G3 * 1024];              // pre-split W_ih lo

__device__ __forceinline__ float tf32_round(float f) {
    uint32_t r;
    asm("cvt.rna.tf32.f32 %0, %1;" : "=r"(r) : "f"(f));
    return __uint_as_float(r);
}
__device__ __forceinline__ void tf32_split(float x, float& hi, float& lo) {
    hi = tf32_round(x);
    lo = tf32_round(x - hi);
}
__device__ __forceinline__ void cp_async16(uint32_t smem_addr, const void* gptr) {
    asm volatile("cp.async.cg.shared.global [%0], [%1], 16;" :: "r"(smem_addr), "l"(gptr));
}

#define MMA_TF32(d, a, b)                                                       \
    asm volatile(                                                               \
        "mma.sync.aligned.m16n8k8.row.col.f32.tf32.tf32.f32 "                   \
        "{%0,%1,%2,%3}, {%4,%5,%6,%7}, {%8,%9}, {%0,%1,%2,%3};"                 \
        : "+f"(d[0]), "+f"(d[1]), "+f"(d[2]), "+f"(d[3])                        \
        : "r"(a[0]), "r"(a[1]), "r"(a[2]), "r"(a[3]), "r"(b[0]), "r"(b[1]))

#define BM 128
#define BN 128
#define BK 16
#define LDP 20
#define TILE_F (BM * LDP)
#define STAGE_F (4 * TILE_F)
#define GEMM_SMEM_BYTES (2 * STAGE_F * 4)   // 81920

// ---------------------------------------------------------------------------
// Kernel 0: one-shot tf32 split of enc and W_ih into hi/lo (VERBATIM r14).
// ---------------------------------------------------------------------------
__global__ void __launch_bounds__(256) split_ab(const float4* __restrict__ A,
                                                const float4* __restrict__ W)
{
    const int NA4 = 16384000;
    const int NW4 = 196608;
    float4* Ah4 = (float4*)g_Ah;  float4* Al4 = (float4*)g_Al;
    float4* Bh4 = (float4*)g_Bh;  float4* Bl4 = (float4*)g_Bl;
    for (int i = blockIdx.x * blockDim.x + threadIdx.x; i < NA4 + NW4;
         i += gridDim.x * blockDim.x) {
        bool isA = i < NA4;
        float4 v = isA ? __ldg(A + i) : __ldg(W + (i - NA4));
        float4 h, l;
        tf32_split(v.x, h.x, l.x);
        tf32_split(v.y, h.y, l.y);
        tf32_split(v.z, h.z, l.z);
        tf32_split(v.w, h.w, l.w);
        if (isA) { Ah4[i] = h; Al4[i] = l; }
        else     { Bh4[i - NA4] = h; Bl4[i - NA4] = l; }
    }
}

// ---------------------------------------------------------------------------
// Kernel 1: 3xTF32 tensor-core GEMM, cp.async double-buffered (VERBATIM r14).
// ---------------------------------------------------------------------------
__global__ void __launch_bounds__(256) gemm_xp_tc(const float* __restrict__ bih)
{
    extern __shared__ float smg[];

    const int tid  = threadIdx.x;
    const int m0   = blockIdx.y * BM;
    const int g0   = blockIdx.x * BN;
    const int warp = tid >> 5;
    const int lane = tid & 31;
    const int wm   = (warp & 1) * 64;
    const int wn   = (warp >> 1) * 32;
    const int lr_  = lane >> 2;
    const int lc_  = lane & 3;

    const uint32_t sm_u = (uint32_t)__cvta_generic_to_shared(smg);

    const int mat   = warp >> 1;
    const int rhalf = (warp & 1) * 64;
    const float* gsrc =
        (mat == 0) ? (g_Ah + (size_t)m0 * H_DIM) :
        (mat == 1) ? (g_Al + (size_t)m0 * H_DIM) :
        (mat == 2) ? (g_Bh + (size_t)g0 * H_DIM) :
                     (g_Bl + (size_t)g0 * H_DIM);

    auto issue_tile = [&](int stage, int k0) {
        #pragma unroll
        for (int i = 0; i < 8; ++i) {
            int chunk = i * 32 + lane;
            int rowl  = chunk >> 2;
            int ch    = chunk & 3;
            int row   = rhalf + rowl;
            const float* src = gsrc + (size_t)row * H_DIM + k0 + ch * 4;
            uint32_t dst = sm_u +
                (uint32_t)((stage * STAGE_F + mat * TILE_F + row * LDP + ch * 4) * 4);
            cp_async16(dst, src);
        }
        asm volatile("cp.async.commit_group;" ::: "memory");
    };

    float acc[4][4][4];
    #pragma unroll
    for (int mi = 0; mi < 4; ++mi)
        #pragma unroll
        for (int ni = 0; ni < 4; ++ni)
            #pragma unroll
            for (int r = 0; r < 4; ++r) acc[mi][ni][r] = 0.f;

    issue_tile(0, 0);
    issue_tile(1, BK);

    int p = 0;
    for (int it = 0; it < H_DIM / BK; ++it) {
        asm volatile("cp.async.wait_group 1;" ::: "memory");
        __syncthreads();

        const float* S  = smg + p * STAGE_F;
        const float* Ah = S;
        const float* Al = S + TILE_F;
        const float* Bh = S + 2 * TILE_F;
        const float* Bl = S + 3 * TILE_F;

        #pragma unroll
        for (int kk = 0; kk < 2; ++kk) {
            const int kb = kk * 8;
            uint32_t afh[4][4], afl[4][4];
            #pragma unroll
            for (int mi = 0; mi < 4; ++mi) {
                int r = wm + mi * 16 + lr_;
                afh[mi][0] = __float_as_uint(Ah[r * LDP + kb + lc_]);
                afh[mi][1] = __float_as_uint(Ah[(r + 8) * LDP + kb + lc_]);
                afh[mi][2] = __float_as_uint(Ah[r * LDP + kb + lc_ + 4]);
                afh[mi][3] = __float_as_uint(Ah[(r + 8) * LDP + kb + lc_ + 4]);
                afl[mi][0] = __float_as_uint(Al[r * LDP + kb + lc_]);
                afl[mi][1] = __float_as_uint(Al[(r + 8) * LDP + kb + lc_]);
                afl[mi][2] = __float_as_uint(Al[r * LDP + kb + lc_ + 4]);
                afl[mi][3] = __float_as_uint(Al[(r + 8) * LDP + kb + lc_ + 4]);
            }
            uint32_t bfh[4][2], bfl[4][2];
            #pragma unroll
            for (int ni = 0; ni < 4; ++ni) {
                int cn = wn + ni * 8 + lr_;
                bfh[ni][0] = __float_as_uint(Bh[cn * LDP + kb + lc_]);
                bfh[ni][1] = __float_as_uint(Bh[cn * LDP + kb + lc_ + 4]);
                bfl[ni][0] = __float_as_uint(Bl[cn * LDP + kb + lc_]);
                bfl[ni][1] = __float_as_uint(Bl[cn * LDP + kb + lc_ + 4]);
            }
            #pragma unroll
            for (int mi = 0; mi < 4; ++mi)
                #pragma unroll
                for (int ni = 0; ni < 4; ++ni) {
                    MMA_TF32(acc[mi][ni], afl[mi], bfh[ni]);
                    MMA_TF32(acc[mi][ni], afh[mi], bfl[ni]);
                    MMA_TF32(acc[mi][ni], afh[mi], bfh[ni]);
                }
        }
        __syncthreads();
        if (it + 2 < H_DIM / BK) issue_tile(p, (it + 2) * BK);
        p ^= 1;
    }

    #pragma unroll
    for (int mi = 0; mi < 4; ++mi) {
        int row = m0 + wm + mi * 16 + lr_;
        int t   = row >> 6;
        int n   = row & 63;
        #pragma unroll
        for (int ni = 0; ni < 4; ++ni) {
            int col = g0 + wn + ni * 8 + 2 * lc_;
            float bv0 = __ldg(&bih[col]);
            float bv1 = __ldg(&bih[col + 1]);
            float* p0 = &g_xpT[((size_t)t * G3 + col) * N_B];
            float* p1 = &g_xpT[((size_t)t * G3 + col + 1) * N_B];
            p0[n]     = acc[mi][ni][0] + bv0;
            p1[n]     = acc[mi][ni][1] + bv1;
            p0[n + 8] = acc[mi][ni][2] + bv0;
            p1[n + 8] = acc[mi][ni][3] + bv1;
        }
    }
}

// ---------------------------------------------------------------------------
// Kernel 2: cluster-parallel GRU scan — r14 dot engine (scalar fmaf, W in
// smem [g][k][ch]); ONE change vs r14: the cluster barrier is SPLIT into
// arrive -> (out store + xp prefetch for t+1) -> wait, hiding local work
// and arrival skew inside the barrier window.
// ---------------------------------------------------------------------------
#define CL_CTAS 8
#define SCAN_THR 256
#define W_FLOATS   24576
#define H_FLOATS   1024
#define RED_STRIDE 13
#define RED_FLOATS (SCAN_THR * RED_STRIDE)
#define SCAN_SMEM_BYTES ((W_FLOATS + H_FLOATS + RED_FLOATS) * 4)

#define CLUSTER_ARRIVE() \
    asm volatile("barrier.cluster.arrive.aligned;" ::: "memory")
#define CLUSTER_WAIT() \
    asm volatile("barrier.cluster.wait.aligned;" ::: "memory")

__device__ __forceinline__ float fast_sigmoid(float x) {
    return __fdividef(1.f, 1.f + __expf(-x));
}
__device__ __forceinline__ float fast_tanh(float x) {
    return 1.f - __fdividef(2.f, __expf(2.f * x) + 1.f);
}

__global__ void __launch_bounds__(SCAN_THR, 1) __cluster_dims__(CL_CTAS, 1, 1)
scan_cluster(const float* __restrict__ Whh,
             const float* __restrict__ bhh,
             float* __restrict__ out)
{
    extern __shared__ float sm[];
    float* W_s = sm;                    // [3][256][32]
    float* h_s = sm + W_FLOATS;         // [4][256]
    float* red = h_s + H_FLOATS;        // [256][13]

    const int tid  = threadIdx.x;
    const int cl   = blockIdx.x >> 3;
    const int rank = blockIdx.x & 7;
    const int chl  = tid & 31;
    const int ks   = tid >> 5;
    const int k0   = ks * 32;

    const int rrow = tid >> 5;          // reducer role (tid<128)
    const int rchl = tid & 31;
    const int c_g  = rank * 32 + rchl;
    const int n_g  = cl * 4 + rrow;

    for (int idx = tid; idx < W_FLOATS; idx += SCAN_THR) {
        int lchl = idx & 31;
        int k    = (idx >> 5) & 255;
        int g    = idx >> 13;
        W_s[idx] = __ldg(&Whh[((size_t)(g * C_DIM + rank * 32 + lchl)) * C_DIM + k]);
    }
    #pragma unroll
    for (int i = 0; i < H_FLOATS / SCAN_THR; ++i)
        h_s[tid + i * SCAN_THR] = 0.f;

    float bhr = 0.f, bhz = 0.f, bhn = 0.f;
    if (tid < 128) {
        bhr = __ldg(&bhh[c_g]);
        bhz = __ldg(&bhh[C_DIM + c_g]);
        bhn = __ldg(&bhh[2 * C_DIM + c_g]);
    }
    __syncthreads();

    // prefetch xp gates for t = 0
    float xr = 0.f, xz = 0.f, xn = 0.f;
    if (tid < 128) {
        xr = __ldg(g_xpT + (size_t)(0 * C_DIM + c_g) * N_B + n_g);
        xz = __ldg(g_xpT + (size_t)(1 * C_DIM + c_g) * N_B + n_g);
        xn = __ldg(g_xpT + (size_t)(2 * C_DIM + c_g) * N_B + n_g);
    }

    for (int t = 0; t < T_STEPS; ++t) {
        float acc[4][3];
        #pragma unroll
        for (int rw = 0; rw < 4; ++rw)
            #pragma unroll
            for (int g = 0; g < 3; ++g) acc[rw][g] = 0.f;

        if (t > 0) {
            #pragma unroll
            for (int kk = 0; kk < 32; kk += 4) {
                const int k = k0 + kk;
                float4 h0 = *(const float4*)&h_s[k];
                float4 h1 = *(const float4*)&h_s[256 + k];
                float4 h2 = *(const float4*)&h_s[512 + k];
                float4 h3 = *(const float4*)&h_s[768 + k];
                const float hv[4][4] = {
                    {h0.x, h0.y, h0.z, h0.w},
                    {h1.x, h1.y, h1.z, h1.w},
                    {h2.x, h2.y, h2.z, h2.w},
                    {h3.x, h3.y, h3.z, h3.w}};
                #pragma unroll
                for (int g = 0; g < 3; ++g) {
                    const float* wp = &W_s[((g * 256 + k) << 5) + chl];
                    #pragma unroll
                    for (int q = 0; q < 4; ++q) {
                        float w = wp[q << 5];
                        acc[0][g] = fmaf(hv[0][q], w, acc[0][g]);
                        acc[1][g] = fmaf(hv[1][q], w, acc[1][g]);
                        acc[2][g] = fmaf(hv[2][q], w, acc[2][g]);
                        acc[3][g] = fmaf(hv[3][q], w, acc[3][g]);
                    }
                }
            }
        }

        {
            float* rp = &red[tid * RED_STRIDE];
            #pragma unroll
            for (int rw = 0; rw < 4; ++rw)
                #pragma unroll
                for (int g = 0; g < 3; ++g) rp[rw * 3 + g] = acc[rw][g];
        }
        __syncthreads();

        float hnew = 0.f;
        if (tid < 128) {
            float sr = 0.f, sz = 0.f, sn = 0.f;
            #pragma unroll
            for (int kq = 0; kq < 8; ++kq) {
                const float* rp = &red[((kq << 5) + rchl) * RED_STRIDE + rrow * 3];
                sr += rp[0];
                sz += rp[1];
                sn += rp[2];
            }
            float h_old = h_s[rrow * 256 + c_g];

            float r  = fast_sigmoid(xr + sr + bhr);
            float z  = fast_sigmoid(xz + sz + bhz);
            float nt = fast_tanh(xn + r * (sn + bhn));
            hnew = nt + z * (h_old - nt);

            __stcg(&g_hEx[cl * 1024 + rrow * 256 + c_g], hnew);
        }

        // split barrier: release our g_hEx stores, then overlap local work
        // (out store, next xp prefetch) with other CTAs' arrival skew.
        CLUSTER_ARRIVE();

        if (tid < 128) {
            out[((size_t)t * N_B + n_g) * C_DIM + c_g] = hnew;
            if (t < T_STEPS - 1) {
                const float* xp = g_xpT + (size_t)(t + 1) * (G3 * N_B);
                xr = __ldg(xp + (0 * C_DIM + c_g) * N_B + n_g);
                xz = __ldg(xp + (1 * C_DIM + c_g) * N_B + n_g);
                xn = __ldg(xp + (2 * C_DIM + c_g) * N_B + n_g);
            }
        }

        CLUSTER_WAIT();   // acquire: peers' g_hEx stores now visible

        if (t < T_STEPS - 1) {
            ((float4*)h_s)[tid] = __ldcg((const float4*)(g_hEx + cl * 1024) + tid);
            __syncthreads();
        }
    }
}

// ---------------------------------------------------------------------------
// Kernel 3: log-softmax over c, in place on [t][n][c]. Warp per row. (r14)
// ---------------------------------------------------------------------------
__global__ void __launch_bounds__(256) logsoftmax_kernel(float* __restrict__ out)
{
    const int t    = blockIdx.x;
    const int w    = threadIdx.x >> 5;
    const int lane = threadIdx.x & 31;

    #pragma unroll
    for (int i = 0; i < 8; ++i) {
        const int n = w * 8 + i;
        float* row = out + ((size_t)t * N_B + n) * C_DIM;
        float4 a = *(const float4*)&row[lane * 4];
        float4 b = *(const float4*)&row[128 + lane * 4];

        float mx = fmaxf(fmaxf(fmaxf(a.x, a.y), fmaxf(a.z, a.w)),
                         fmaxf(fmaxf(b.x, b.y), fmaxf(b.z, b.w)));
        #pragma unroll
        for (int s = 16; s > 0; s >>= 1)
            mx = fmaxf(mx, __shfl_xor_sync(0xffffffffu, mx, s));

        float sum = expf(a.x - mx) + expf(a.y - mx) + expf(a.z - mx) + expf(a.w - mx)
                  + expf(b.x - mx) + expf(b.y - mx) + expf(b.z - mx) + expf(b.w - mx);
        #pragma unroll
        for (int s = 16; s > 0; s >>= 1)
            sum += __shfl_xor_sync(0xffffffffu, sum, s);

        float lse = mx + logf(sum);
        a.x -= lse; a.y -= lse; a.z -= lse; a.w -= lse;
        b.x -= lse; b.y -= lse; b.z -= lse; b.w -= lse;
        *(float4*)&row[lane * 4]       = a;
        *(float4*)&row[128 + lane * 4] = b;
    }
}

extern "C" void kernel_launch(void* const* d_in, const int* in_sizes, int n_in,
                              void* d_out, int out_size)
{
    const float* enc  = (const float*)d_in[0];
    const float* W_ih = (const float*)d_in[1];
    const float* W_hh = (const float*)d_in[2];
    const float* b_ih = (const float*)d_in[3];
    const float* b_hh = (const float*)d_in[4];
    float* out = (float*)d_out;

    cudaFuncSetAttribute(gemm_xp_tc, cudaFuncAttributeMaxDynamicSharedMemorySize, GEMM_SMEM_BYTES);
    cudaFuncSetAttribute(scan_cluster, cudaFuncAttributeMaxDynamicSharedMemorySize, SCAN_SMEM_BYTES);

    split_ab<<<8192, 256>>>((const float4*)enc, (const float4*)W_ih);
    gemm_xp_tc<<<dim3(G3 / BN, (T_STEPS * N_B) / BM), 256, GEMM_SMEM_BYTES>>>(b_ih);
    scan_cluster<<<128, SCAN_THR, SCAN_SMEM_BYTES>>>(W_hh, b_hh, out);
    logsoftmax_kernel<<<T_STEPS, 256>>>(out);
}

// round 17
// speedup vs baseline: 1.3444x; 1.1615x over previous
#include <cuda_runtime.h>
#include <math.h>
#include <stdint.h>

#define T_STEPS 1000
#define N_B     64
#define H_DIM   1024
#define C_DIM   256
#define G3      768

// Scratch (__device__ globals; allocation-free rule)
__device__ float g_xpT[(size_t)T_STEPS * N_B * G3];   // [t][n][gate*256+c]  (coalesced for scan)
__device__ float g_hEx[16 * 1024];                     // per-cluster h exchange
__device__ float g_Ah[(size_t)64000 * 1024];           // pre-split enc (tf32 hi)
__device__ float g_Al[(size_t)64000 * 1024];           // pre-split enc (tf32 lo)
__device__ float g_Bh[(size_t)G3 * 1024];              // pre-split W_ih hi
__device__ float g_Bl[(size_t)G3 * 1024];              // pre-split W_ih lo

__device__ __forceinline__ float tf32_round(float f) {
    uint32_t r;
    asm("cvt.rna.tf32.f32 %0, %1;" : "=r"(r) : "f"(f));
    return __uint_as_float(r);
}
__device__ __forceinline__ void tf32_split(float x, float& hi, float& lo) {
    hi = tf32_round(x);
    lo = tf32_round(x - hi);
}
__device__ __forceinline__ void cp_async16(uint32_t smem_addr, const void* gptr) {
    asm volatile("cp.async.cg.shared.global [%0], [%1], 16;" :: "r"(smem_addr), "l"(gptr));
}

#define MMA_TF32(d, a, b)                                                       \
    asm volatile(                                                               \
        "mma.sync.aligned.m16n8k8.row.col.f32.tf32.tf32.f32 "                   \
        "{%0,%1,%2,%3}, {%4,%5,%6,%7}, {%8,%9}, {%0,%1,%2,%3};"                 \
        : "+f"(d[0]), "+f"(d[1]), "+f"(d[2]), "+f"(d[3])                        \
        : "r"(a[0]), "r"(a[1]), "r"(a[2]), "r"(a[3]), "r"(b[0]), "r"(b[1]))

#define BM 128
#define BN 128
#define BK 16
#define LDP 20
#define TILE_F (BM * LDP)
#define STAGE_F (4 * TILE_F)
#define GEMM_SMEM_BYTES (2 * STAGE_F * 4)   // 81920

// ---------------------------------------------------------------------------
// Kernel 0: one-shot tf32 split of enc and W_ih into hi/lo (VERBATIM r14).
// ---------------------------------------------------------------------------
__global__ void __launch_bounds__(256) split_ab(const float4* __restrict__ A,
                                                const float4* __restrict__ W)
{
    const int NA4 = 16384000;
    const int NW4 = 196608;
    float4* Ah4 = (float4*)g_Ah;  float4* Al4 = (float4*)g_Al;
    float4* Bh4 = (float4*)g_Bh;  float4* Bl4 = (float4*)g_Bl;
    for (int i = blockIdx.x * blockDim.x + threadIdx.x; i < NA4 + NW4;
         i += gridDim.x * blockDim.x) {
        bool isA = i < NA4;
        float4 v = isA ? __ldg(A + i) : __ldg(W + (i - NA4));
        float4 h, l;
        tf32_split(v.x, h.x, l.x);
        tf32_split(v.y, h.y, l.y);
        tf32_split(v.z, h.z, l.z);
        tf32_split(v.w, h.w, l.w);
        if (isA) { Ah4[i] = h; Al4[i] = l; }
        else     { Bh4[i - NA4] = h; Bl4[i - NA4] = l; }
    }
}

// ---------------------------------------------------------------------------
// Kernel 1: 3xTF32 tensor-core GEMM, cp.async double-buffered (r14 mainloop);
// epilogue now writes xp in [t][n][g3] layout with contiguous float2 stores.
// ---------------------------------------------------------------------------
__global__ void __launch_bounds__(256) gemm_xp_tc(const float* __restrict__ bih)
{
    extern __shared__ float smg[];

    const int tid  = threadIdx.x;
    const int m0   = blockIdx.y * BM;
    const int g0   = blockIdx.x * BN;
    const int warp = tid >> 5;
    const int lane = tid & 31;
    const int wm   = (warp & 1) * 64;
    const int wn   = (warp >> 1) * 32;
    const int lr_  = lane >> 2;
    const int lc_  = lane & 3;

    const uint32_t sm_u = (uint32_t)__cvta_generic_to_shared(smg);

    const int mat   = warp >> 1;
    const int rhalf = (warp & 1) * 64;
    const float* gsrc =
        (mat == 0) ? (g_Ah + (size_t)m0 * H_DIM) :
        (mat == 1) ? (g_Al + (size_t)m0 * H_DIM) :
        (mat == 2) ? (g_Bh + (size_t)g0 * H_DIM) :
                     (g_Bl + (size_t)g0 * H_DIM);

    auto issue_tile = [&](int stage, int k0) {
        #pragma unroll
        for (int i = 0; i < 8; ++i) {
            int chunk = i * 32 + lane;
            int rowl  = chunk >> 2;
            int ch    = chunk & 3;
            int row   = rhalf + rowl;
            const float* src = gsrc + (size_t)row * H_DIM + k0 + ch * 4;
            uint32_t dst = sm_u +
                (uint32_t)((stage * STAGE_F + mat * TILE_F + row * LDP + ch * 4) * 4);
            cp_async16(dst, src);
        }
        asm volatile("cp.async.commit_group;" ::: "memory");
    };

    float acc[4][4][4];
    #pragma unroll
    for (int mi = 0; mi < 4; ++mi)
        #pragma unroll
        for (int ni = 0; ni < 4; ++ni)
            #pragma unroll
            for (int r = 0; r < 4; ++r) acc[mi][ni][r] = 0.f;

    issue_tile(0, 0);
    issue_tile(1, BK);

    int p = 0;
    for (int it = 0; it < H_DIM / BK; ++it) {
        asm volatile("cp.async.wait_group 1;" ::: "memory");
        __syncthreads();

        const float* S  = smg + p * STAGE_F;
        const float* Ah = S;
        const float* Al = S + TILE_F;
        const float* Bh = S + 2 * TILE_F;
        const float* Bl = S + 3 * TILE_F;

        #pragma unroll
        for (int kk = 0; kk < 2; ++kk) {
            const int kb = kk * 8;
            uint32_t afh[4][4], afl[4][4];
            #pragma unroll
            for (int mi = 0; mi < 4; ++mi) {
                int r = wm + mi * 16 + lr_;
                afh[mi][0] = __float_as_uint(Ah[r * LDP + kb + lc_]);
                afh[mi][1] = __float_as_uint(Ah[(r + 8) * LDP + kb + lc_]);
                afh[mi][2] = __float_as_uint(Ah[r * LDP + kb + lc_ + 4]);
                afh[mi][3] = __float_as_uint(Ah[(r + 8) * LDP + kb + lc_ + 4]);
                afl[mi][0] = __float_as_uint(Al[r * LDP + kb + lc_]);
                afl[mi][1] = __float_as_uint(Al[(r + 8) * LDP + kb + lc_]);
                afl[mi][2] = __float_as_uint(Al[r * LDP + kb + lc_ + 4]);
                afl[mi][3] = __float_as_uint(Al[(r + 8) * LDP + kb + lc_ + 4]);
            }
            uint32_t bfh[4][2], bfl[4][2];
            #pragma unroll
            for (int ni = 0; ni < 4; ++ni) {
                int cn = wn + ni * 8 + lr_;
                bfh[ni][0] = __float_as_uint(Bh[cn * LDP + kb + lc_]);
                bfh[ni][1] = __float_as_uint(Bh[cn * LDP + kb + lc_ + 4]);
                bfl[ni][0] = __float_as_uint(Bl[cn * LDP + kb + lc_]);
                bfl[ni][1] = __float_as_uint(Bl[cn * LDP + kb + lc_ + 4]);
            }
            #pragma unroll
            for (int mi = 0; mi < 4; ++mi)
                #pragma unroll
                for (int ni = 0; ni < 4; ++ni) {
                    MMA_TF32(acc[mi][ni], afl[mi], bfh[ni]);
                    MMA_TF32(acc[mi][ni], afh[mi], bfl[ni]);
                    MMA_TF32(acc[mi][ni], afh[mi], bfh[ni]);
                }
        }
        __syncthreads();
        if (it + 2 < H_DIM / BK) issue_tile(p, (it + 2) * BK);
        p ^= 1;
    }

    // Epilogue: [t][n][g3] layout, contiguous float2 stores.
    #pragma unroll
    for (int mi = 0; mi < 4; ++mi) {
        int row = m0 + wm + mi * 16 + lr_;
        int t   = row >> 6;
        int n   = row & 63;
        #pragma unroll
        for (int ni = 0; ni < 4; ++ni) {
            int col = g0 + wn + ni * 8 + 2 * lc_;
            float bv0 = __ldg(&bih[col]);
            float bv1 = __ldg(&bih[col + 1]);
            float2 v0 = make_float2(acc[mi][ni][0] + bv0, acc[mi][ni][1] + bv1);
            float2 v1 = make_float2(acc[mi][ni][2] + bv0, acc[mi][ni][3] + bv1);
            *(float2*)&g_xpT[((size_t)t * N_B + n) * G3 + col]     = v0;
            *(float2*)&g_xpT[((size_t)t * N_B + n + 8) * G3 + col] = v1;
        }
    }
}

// ---------------------------------------------------------------------------
// Kernel 2: cluster-parallel GRU scan — VERBATIM r14 structure (combined
// CLUSTER_SYNC, scalar fmaf dot, fast gates); ONLY the xp read addresses
// change to the new coalesced [t][n][g3] layout (lanes vary c -> contiguous).
// ---------------------------------------------------------------------------
#define CL_CTAS 8
#define SCAN_THR 256
#define W_FLOATS   24576
#define H_FLOATS   1024
#define RED_STRIDE 13
#define RED_FLOATS (SCAN_THR * RED_STRIDE)
#define SCAN_SMEM_BYTES ((W_FLOATS + H_FLOATS + RED_FLOATS) * 4)

#define CLUSTER_SYNC() do {                                          \
    asm volatile("barrier.cluster.arrive.aligned;" ::: "memory");    \
    asm volatile("barrier.cluster.wait.aligned;" ::: "memory");      \
} while (0)

__device__ __forceinline__ float fast_sigmoid(float x) {
    return __fdividef(1.f, 1.f + __expf(-x));
}
__device__ __forceinline__ float fast_tanh(float x) {
    return 1.f - __fdividef(2.f, __expf(2.f * x) + 1.f);
}

__global__ void __launch_bounds__(SCAN_THR, 1) __cluster_dims__(CL_CTAS, 1, 1)
scan_cluster(const float* __restrict__ Whh,
             const float* __restrict__ bhh,
             float* __restrict__ out)
{
    extern __shared__ float sm[];
    float* W_s = sm;                    // [3][256][32]
    float* h_s = sm + W_FLOATS;         // [4][256]
    float* red = h_s + H_FLOATS;        // [256][13]

    const int tid  = threadIdx.x;
    const int cl   = blockIdx.x >> 3;
    const int rank = blockIdx.x & 7;
    const int chl  = tid & 31;
    const int ks   = tid >> 5;
    const int k0   = ks * 32;

    const int rrow = tid >> 5;          // reducer role (tid<128)
    const int rchl = tid & 31;
    const int c_g  = rank * 32 + rchl;
    const int n_g  = cl * 4 + rrow;

    for (int idx = tid; idx < W_FLOATS; idx += SCAN_THR) {
        int lchl = idx & 31;
        int k    = (idx >> 5) & 255;
        int g    = idx >> 13;
        W_s[idx] = __ldg(&Whh[((size_t)(g * C_DIM + rank * 32 + lchl)) * C_DIM + k]);
    }
    #pragma unroll
    for (int i = 0; i < H_FLOATS / SCAN_THR; ++i)
        h_s[tid + i * SCAN_THR] = 0.f;

    float bhr = 0.f, bhz = 0.f, bhn = 0.f;
    if (tid < 128) {
        bhr = __ldg(&bhh[c_g]);
        bhz = __ldg(&bhh[C_DIM + c_g]);
        bhn = __ldg(&bhh[2 * C_DIM + c_g]);
    }
    __syncthreads();

    for (int t = 0; t < T_STEPS; ++t) {
        // coalesced xp gate loads: [t][n][g3], lanes vary c -> contiguous 128B
        float xr = 0.f, xz = 0.f, xn = 0.f;
        if (tid < 128) {
            const float* xp = g_xpT + ((size_t)t * N_B + n_g) * G3;
            xr = __ldg(xp + 0 * C_DIM + c_g);
            xz = __ldg(xp + 1 * C_DIM + c_g);
            xn = __ldg(xp + 2 * C_DIM + c_g);
        }

        float acc[4][3];
        #pragma unroll
        for (int rw = 0; rw < 4; ++rw)
            #pragma unroll
            for (int g = 0; g < 3; ++g) acc[rw][g] = 0.f;

        if (t > 0) {
            #pragma unroll
            for (int kk = 0; kk < 32; kk += 4) {
                const int k = k0 + kk;
                float4 h0 = *(const float4*)&h_s[k];
                float4 h1 = *(const float4*)&h_s[256 + k];
                float4 h2 = *(const float4*)&h_s[512 + k];
                float4 h3 = *(const float4*)&h_s[768 + k];
                const float hv[4][4] = {
                    {h0.x, h0.y, h0.z, h0.w},
                    {h1.x, h1.y, h1.z, h1.w},
                    {h2.x, h2.y, h2.z, h2.w},
                    {h3.x, h3.y, h3.z, h3.w}};
                #pragma unroll
                for (int g = 0; g < 3; ++g) {
                    const float* wp = &W_s[((g * 256 + k) << 5) + chl];
                    #pragma unroll
                    for (int q = 0; q < 4; ++q) {
                        float w = wp[q << 5];
                        acc[0][g] = fmaf(hv[0][q], w, acc[0][g]);
                        acc[1][g] = fmaf(hv[1][q], w, acc[1][g]);
                        acc[2][g] = fmaf(hv[2][q], w, acc[2][g]);
                        acc[3][g] = fmaf(hv[3][q], w, acc[3][g]);
                    }
                }
            }
        }

        {
            float* rp = &red[tid * RED_STRIDE];
            #pragma unroll
            for (int rw = 0; rw < 4; ++rw)
                #pragma unroll
                for (int g = 0; g < 3; ++g) rp[rw * 3 + g] = acc[rw][g];
        }
        __syncthreads();

        float hnew = 0.f;
        if (tid < 128) {
            float sr = 0.f, sz = 0.f, sn = 0.f;
            #pragma unroll
            for (int kq = 0; kq < 8; ++kq) {
                const float* rp = &red[((kq << 5) + rchl) * RED_STRIDE + rrow * 3];
                sr += rp[0];
                sz += rp[1];
                sn += rp[2];
            }
            float h_old = h_s[rrow * 256 + c_g];

            float r  = fast_sigmoid(xr + sr + bhr);
            float z  = fast_sigmoid(xz + sz + bhz);
            float nt = fast_tanh(xn + r * (sn + bhn));
            hnew = nt + z * (h_old - nt);

            __stcg(&g_hEx[cl * 1024 + rrow * 256 + c_g], hnew);
        }

        CLUSTER_SYNC();   // arrive=release / wait=acquire orders g_hEx stores

        if (tid < 128)
            out[((size_t)t * N_B + n_g) * C_DIM + c_g] = hnew;  // coalesced

        if (t < T_STEPS - 1) {
            ((float4*)h_s)[tid] = __ldcg((const float4*)(g_hEx + cl * 1024) + tid);
            __syncthreads();
        }
    }
}

// ---------------------------------------------------------------------------
// Kernel 3: log-softmax over c, in place on [t][n][c]. Warp per row. (r14)
// ---------------------------------------------------------------------------
__global__ void __launch_bounds__(256) logsoftmax_kernel(float* __restrict__ out)
{
    const int t    = blockIdx.x;
    const int w    = threadIdx.x >> 5;
    const int lane = threadIdx.x & 31;

    #pragma unroll
    for (int i = 0; i < 8; ++i) {
        const int n = w * 8 + i;
        float* row = out + ((size_t)t * N_B + n) * C_DIM;
        float4 a = *(const float4*)&row[lane * 4];
        float4 b = *(const float4*)&row[128 + lane * 4];

        float mx = fmaxf(fmaxf(fmaxf(a.x, a.y), fmaxf(a.z, a.w)),
                         fmaxf(fmaxf(b.x, b.y), fmaxf(b.z, b.w)));
        #pragma unroll
        for (int s = 16; s > 0; s >>= 1)
            mx = fmaxf(mx, __shfl_xor_sync(0xffffffffu, mx, s));

        float sum = expf(a.x - mx) + expf(a.y - mx) + expf(a.z - mx) + expf(a.w - mx)
                  + expf(b.x - mx) + expf(b.y - mx) + expf(b.z - mx) + expf(b.w - mx);
        #pragma unroll
        for (int s = 16; s > 0; s >>= 1)
            sum += __shfl_xor_sync(0xffffffffu, sum, s);

        float lse = mx + logf(sum);
        a.x -= lse; a.y -= lse; a.z -= lse; a.w -= lse;
        b.x -= lse; b.y -= lse; b.z -= lse; b.w -= lse;
        *(float4*)&row[lane * 4]       = a;
        *(float4*)&row[128 + lane * 4] = b;
    }
}

extern "C" void kernel_launch(void* const* d_in, const int* in_sizes, int n_in,
                              void* d_out, int out_size)
{
    const float* enc  = (const float*)d_in[0];
    const float* W_ih = (const float*)d_in[1];
    const float* W_hh = (const float*)d_in[2];
    const float* b_ih = (const float*)d_in[3];
    const float* b_hh = (const float*)d_in[4];
    float* out = (float*)d_out;

    cudaFuncSetAttribute(gemm_xp_tc, cudaFuncAttributeMaxDynamicSharedMemorySize, GEMM_SMEM_BYTES);
    cudaFuncSetAttribute(scan_cluster, cudaFuncAttributeMaxDynamicSharedMemorySize, SCAN_SMEM_BYTES);

    split_ab<<<8192, 256>>>((const float4*)enc, (const float4*)W_ih);
    gemm_xp_tc<<<dim3(G3 / BN, (T_STEPS * N_B) / BM), 256, GEMM_SMEM_BYTES>>>(b_ih);
    scan_cluster<<<128, SCAN_THR, SCAN_SMEM_BYTES>>>(W_hh, b_hh, out);
    logsoftmax_kernel<<<T_STEPS, 256>>>(out);
}